// round 3
// baseline (speedup 1.0000x reference)
#include <cuda_runtime.h>
#include <math.h>

#define BATCH 2048
#define XF    1024
#define G     16
#define NBLK  512
#define TPB   256
#define CHUNKS 128              // row chunks
#define ROWS_C (BATCH / CHUNKS) // 16 rows per chunk

// Scratch (allocation-free: __device__ globals)
__device__ float g_part0[CHUNKS * XF];
__device__ float g_part1[CHUNKS * XF];
__device__ float g_part2[CHUNKS * XF];
__device__ float g_mean[XF];
__device__ float g_a[XF];
__device__ float g_bv[XF];

__device__ unsigned g_count = 0;
__device__ unsigned g_gen   = 0;

// Grid-wide barrier: sense via monotone generation counter (replay-safe:
// g_count returns to 0 after every barrier; g_gen only ever compared for
// inequality against the value captured at entry).
__device__ __forceinline__ void grid_barrier() {
    __threadfence();                 // make this block's stores visible
    __syncthreads();
    if (threadIdx.x == 0) {
        unsigned gen = atomicAdd(&g_gen, 0u);
        if (atomicAdd(&g_count, 1u) == NBLK - 1u) {
            atomicExch(&g_count, 0u);
            __threadfence();
            atomicAdd(&g_gen, 1u);   // release
        } else {
            while (atomicAdd(&g_gen, 0u) == gen) { }
        }
        __threadfence();             // acquire side
    }
    __syncthreads();
}

__global__ __launch_bounds__(TPB, 4)
void fused_kernel(const float* __restrict__ xf,
                  const float* __restrict__ wp,
                  float* __restrict__ out) {
    const int tid = threadIdx.x;
    const int b   = blockIdx.x;

    // ---- Phase 1: per-column partial sums (512 blocks, 16 rows each) ----
    {
        int cg = b & 3, chunk = b >> 2;
        int col = cg * TPB + tid;
        const float* p = xf + (size_t)(chunk * ROWS_C) * XF + col;
        float s = 0.f;
#pragma unroll
        for (int r = 0; r < ROWS_C; r++) s += p[(size_t)r * XF];
        g_part0[chunk * XF + col] = s;
    }
    grid_barrier();

    // ---- Phase 2a: fold partials -> mean (blocks 0..3) ----
    if (b < 4) {
        int col = b * TPB + tid;
        float s = 0.f;
#pragma unroll 16
        for (int r = 0; r < CHUNKS; r++) s += g_part0[r * XF + col];
        g_mean[col] = s * (1.0f / BATCH);
    }
    grid_barrier();

    // ---- Phase 2b: partial sum/sumsq of relu(x - mean) ----
    {
        int cg = b & 3, chunk = b >> 2;
        int col = cg * TPB + tid;
        float m = g_mean[col];
        const float* p = xf + (size_t)(chunk * ROWS_C) * XF + col;
        float s1 = 0.f, s2 = 0.f;
#pragma unroll
        for (int r = 0; r < ROWS_C; r++) {
            float v = p[(size_t)r * XF] - m;
            v = fmaxf(v, 0.f);
            s1 += v;
            s2 += v * v;
        }
        g_part1[chunk * XF + col] = s1;
        g_part2[chunk * XF + col] = s2;
    }
    grid_barrier();

    // ---- Phase 2c: fold stats -> per-column affine a,b (blocks 0..3) ----
    if (b < 4) {
        int col = b * TPB + tid;
        float s1 = 0.f, s2 = 0.f;
#pragma unroll 16
        for (int r = 0; r < CHUNKS; r++) {
            s1 += g_part1[r * XF + col];
            s2 += g_part2[r * XF + col];
        }
        float mu  = s1 * (1.0f / BATCH);
        float var = (s2 - (float)BATCH * mu * mu) * (1.0f / (BATCH - 1));
        float a   = wp[0] * rsqrtf(var);
        g_a[col]  = a;
        g_bv[col] = -a * mu;
    }
    grid_barrier();

    // ---- Phase 3: v = a*relu(x-mean)+b, 16-way tiled streaming stores ----
    {
        int col = tid * 4;                       // 256 float4 spans the row
        float4 m  = *(const float4*)(g_mean + col);
        float4 a  = *(const float4*)(g_a + col);
        float4 bb = *(const float4*)(g_bv + col);
        int row0 = b * (BATCH / NBLK);           // 4 rows per block
#pragma unroll
        for (int j = 0; j < BATCH / NBLK; j++) {
            int row = row0 + j;
            float4 x = *(const float4*)(xf + (size_t)row * XF + col);
            float4 v;
            v.x = fmaxf(x.x - m.x, 0.f) * a.x + bb.x;
            v.y = fmaxf(x.y - m.y, 0.f) * a.y + bb.y;
            v.z = fmaxf(x.z - m.z, 0.f) * a.z + bb.z;
            v.w = fmaxf(x.w - m.w, 0.f) * a.w + bb.w;

            float* orow = out + (size_t)row * (G * XF) + col;
#pragma unroll
            for (int k = 0; k < G; k++)
                __stcs((float4*)(orow + (size_t)k * XF), v);
        }
    }
}

extern "C" void kernel_launch(void* const* d_in, const int* in_sizes, int n_in,
                              void* d_out, int out_size) {
    const float* xf = (const float*)d_in[0];
    const float* wp = (const float*)d_in[1];
    float* out = (float*)d_out;
    fused_kernel<<<NBLK, TPB>>>(xf, wp, out);
}

// round 4
// speedup vs baseline: 1.1540x; 1.1540x over previous
#include <cuda_runtime.h>
#include <math.h>

#define BATCH 2048
#define XF    1024
#define G     16

#define CH1 64                  // sum-partial chunks
#define R1  (BATCH / CH1)       // 32 rows per chunk
#define CH2 64                  // stats-partial chunks
#define R2C (BATCH / CH2)       // 32 rows per chunk

// Scratch (allocation-free: __device__ globals, overwritten every call)
__device__ float g_p0[CH1 * XF];
__device__ float g_p1[CH2 * XF];
__device__ float g_p2[CH2 * XF];
__device__ float g_mean[XF];

// K1: per-column partial sums. grid = CH1 (64), block = 256.
// Thread t owns 4 adjacent columns (float4) -> fully coalesced 16B loads.
__global__ void k1_sum(const float* __restrict__ xf) {
    int tid = threadIdx.x, chunk = blockIdx.x;
    const float4* p = (const float4*)(xf + (size_t)chunk * R1 * XF) + tid;
    float4 s = make_float4(0.f, 0.f, 0.f, 0.f);
#pragma unroll 16
    for (int r = 0; r < R1; r++) {
        float4 x = p[(size_t)r * (XF / 4)];
        s.x += x.x; s.y += x.y; s.z += x.z; s.w += x.w;
    }
    ((float4*)(g_p0 + chunk * XF))[tid] = s;
}

// K2: inline fold of sum partials -> mean (redundant per block, L2-cheap),
// then partial sum/sumsq of relu(x - mean). grid = CH2 (64), block = 256.
__global__ void k2_stats(const float* __restrict__ xf) {
    int tid = threadIdx.x, chunk = blockIdx.x;

    float4 m = make_float4(0.f, 0.f, 0.f, 0.f);
#pragma unroll 16
    for (int r = 0; r < CH1; r++) {
        float4 x = ((const float4*)(g_p0 + r * XF))[tid];
        m.x += x.x; m.y += x.y; m.z += x.z; m.w += x.w;
    }
    const float inv = 1.0f / BATCH;
    m.x *= inv; m.y *= inv; m.z *= inv; m.w *= inv;
    if (chunk == 0) ((float4*)g_mean)[tid] = m;

    const float4* p = (const float4*)(xf + (size_t)chunk * R2C * XF) + tid;
    float4 s1 = make_float4(0.f, 0.f, 0.f, 0.f);
    float4 s2 = make_float4(0.f, 0.f, 0.f, 0.f);
#pragma unroll 16
    for (int r = 0; r < R2C; r++) {
        float4 x = p[(size_t)r * (XF / 4)];
        float vx = fmaxf(x.x - m.x, 0.f);
        float vy = fmaxf(x.y - m.y, 0.f);
        float vz = fmaxf(x.z - m.z, 0.f);
        float vw = fmaxf(x.w - m.w, 0.f);
        s1.x += vx; s1.y += vy; s1.z += vz; s1.w += vw;
        s2.x += vx * vx; s2.y += vy * vy; s2.z += vz * vz; s2.w += vw * vw;
    }
    ((float4*)(g_p1 + chunk * XF))[tid] = s1;
    ((float4*)(g_p2 + chunk * XF))[tid] = s2;
}

// K3: per-block prologue folds stats partials for its 64 columns into
// per-column affine (a,b), then writes the 16-way tiled output.
// grid=(16,16): bx = 64-col tile, by = 128-row tile. block=256.
#define COLS_B 64
#define ROWS_B 128
__global__ void k3_out(const float* __restrict__ xf,
                       const float* __restrict__ wp,
                       float* __restrict__ out) {
    __shared__ float s_m[COLS_B], s_a[COLS_B], s_b[COLS_B];
    int tid = threadIdx.x;
    int col0 = blockIdx.x * COLS_B;

    if (tid < COLS_B) {
        int col = col0 + tid;
        float s1 = 0.f, s2 = 0.f;
#pragma unroll 16
        for (int r = 0; r < CH2; r++) {
            s1 += g_p1[r * XF + col];
            s2 += g_p2[r * XF + col];
        }
        float mu  = s1 * (1.0f / BATCH);
        float var = (s2 - (float)BATCH * mu * mu) * (1.0f / (BATCH - 1));
        float a   = wp[0] * rsqrtf(var);
        s_m[tid] = g_mean[col];
        s_a[tid] = a;
        s_b[tid] = -a * mu;
    }
    __syncthreads();

    int cidx = tid & 15;          // which float4 within 64 cols
    int ridx = tid >> 4;          // 0..15
    int col  = col0 + cidx * 4;

    float4 m = *(const float4*)(s_m + cidx * 4);
    float4 a = *(const float4*)(s_a + cidx * 4);
    float4 b = *(const float4*)(s_b + cidx * 4);

#pragma unroll
    for (int j = 0; j < ROWS_B / 16; j++) {     // 8 rows per thread
        int row = blockIdx.y * ROWS_B + ridx + j * 16;
        float4 x = *(const float4*)(xf + (size_t)row * XF + col);
        float4 v;
        v.x = fmaxf(x.x - m.x, 0.f) * a.x + b.x;
        v.y = fmaxf(x.y - m.y, 0.f) * a.y + b.y;
        v.z = fmaxf(x.z - m.z, 0.f) * a.z + b.z;
        v.w = fmaxf(x.w - m.w, 0.f) * a.w + b.w;

        float* orow = out + (size_t)row * (G * XF) + col;
#pragma unroll
        for (int k = 0; k < G; k++)
            __stcs((float4*)(orow + (size_t)k * XF), v);
    }
}

extern "C" void kernel_launch(void* const* d_in, const int* in_sizes, int n_in,
                              void* d_out, int out_size) {
    const float* xf = (const float*)d_in[0];
    const float* wp = (const float*)d_in[1];
    float* out = (float*)d_out;

    k1_sum<<<CH1, 256>>>(xf);
    k2_stats<<<CH2, 256>>>(xf);
    k3_out<<<dim3(XF / COLS_B, BATCH / ROWS_B), 256>>>(xf, wp, out);
}

// round 6
// speedup vs baseline: 1.2117x; 1.0500x over previous
#include <cuda_runtime.h>
#include <math.h>

#define BATCH 2048
#define XF    1024
#define XF4   (XF / 4)          // 256 float4 per row
#define G     16

#define CH   256                // row chunks for both reduction passes
#define RPC  (BATCH / CH)       // 8 rows per chunk

// Scratch (allocation-free: __device__ globals)
__device__ float g_p0[CH * XF];     // partial sums of xf
__device__ float g_p1[CH * XF];     // partial sums of relu(x-mean)
__device__ float g_p2[CH * XF];     // partial sums of squares
__device__ float g_mean[XF];
__device__ float g_a[XF];
__device__ float g_b[XF];

// ---------------------------------------------------------------------------
// K1: per-column partial sums. grid = CH (256 blocks), block = 256 threads
// spanning the full row width (one float4 column per thread). 8 rows/chunk.
__global__ __launch_bounds__(256) void k1_sum(const float* __restrict__ xf) {
    int tid = threadIdx.x, chunk = blockIdx.x;
    const float4* p = (const float4*)(xf + (size_t)chunk * RPC * XF) + tid;
    float4 s = make_float4(0.f, 0.f, 0.f, 0.f);
#pragma unroll
    for (int r = 0; r < RPC; r++) {
        float4 x = p[(size_t)r * XF4];
        s.x += x.x; s.y += x.y; s.z += x.z; s.w += x.w;
    }
    ((float4*)(g_p0 + chunk * XF))[tid] = s;
}

// ---------------------------------------------------------------------------
// KF1: parallel fold of 256 partials -> column mean.
// grid = 32 blocks, block = 256 (8 warps). Block b covers 32 columns.
// Warp w folds chunks [w*32, w*32+32); lane l -> column b*32+l (coalesced).
__global__ __launch_bounds__(256) void kf1_mean() {
    __shared__ float sh[8][32];
    int lane = threadIdx.x & 31, w = threadIdx.x >> 5;
    int col = blockIdx.x * 32 + lane;
    float s = 0.f;
#pragma unroll
    for (int i = 0; i < 32; i++)
        s += g_p0[(w * 32 + i) * XF + col];
    sh[w][lane] = s;
    __syncthreads();
    if (w == 0) {
        float t = sh[0][lane];
#pragma unroll
        for (int i = 1; i < 8; i++) t += sh[i][lane];
        g_mean[col] = t * (1.0f / BATCH);
    }
}

// ---------------------------------------------------------------------------
// K3: partial sum/sumsq of relu(x - mean). Same shape as K1; xf is L2-hot.
__global__ __launch_bounds__(256) void k3_stats(const float* __restrict__ xf) {
    int tid = threadIdx.x, chunk = blockIdx.x;
    float4 m = ((const float4*)g_mean)[tid];
    const float4* p = (const float4*)(xf + (size_t)chunk * RPC * XF) + tid;
    float4 s1 = make_float4(0.f, 0.f, 0.f, 0.f);
    float4 s2 = make_float4(0.f, 0.f, 0.f, 0.f);
#pragma unroll
    for (int r = 0; r < RPC; r++) {
        float4 x = p[(size_t)r * XF4];
        float vx = fmaxf(x.x - m.x, 0.f);
        float vy = fmaxf(x.y - m.y, 0.f);
        float vz = fmaxf(x.z - m.z, 0.f);
        float vw = fmaxf(x.w - m.w, 0.f);
        s1.x += vx; s1.y += vy; s1.z += vz; s1.w += vw;
        s2.x += vx * vx; s2.y += vy * vy; s2.z += vz * vz; s2.w += vw * vw;
    }
    ((float4*)(g_p1 + chunk * XF))[tid] = s1;
    ((float4*)(g_p2 + chunk * XF))[tid] = s2;
}

// ---------------------------------------------------------------------------
// KF2: parallel fold of s1/s2 -> per-column affine a, b.
__global__ __launch_bounds__(256) void kf2_ab(const float* __restrict__ wp) {
    __shared__ float sh1[8][32];
    __shared__ float sh2[8][32];
    int lane = threadIdx.x & 31, w = threadIdx.x >> 5;
    int col = blockIdx.x * 32 + lane;
    float s1 = 0.f, s2 = 0.f;
#pragma unroll
    for (int i = 0; i < 32; i++) {
        int idx = (w * 32 + i) * XF + col;
        s1 += g_p1[idx];
        s2 += g_p2[idx];
    }
    sh1[w][lane] = s1;
    sh2[w][lane] = s2;
    __syncthreads();
    if (w == 0) {
        float t1 = sh1[0][lane], t2 = sh2[0][lane];
#pragma unroll
        for (int i = 1; i < 8; i++) { t1 += sh1[i][lane]; t2 += sh2[i][lane]; }
        float mu  = t1 * (1.0f / BATCH);
        float var = (t2 - (float)BATCH * mu * mu) * (1.0f / (BATCH - 1));
        float a   = wp[0] * rsqrtf(var);
        g_a[col] = a;
        g_b[col] = -a * mu;
    }
}

// ---------------------------------------------------------------------------
// K5: v = a*relu(x-mean)+b, write 16 tiled copies with streaming stores.
// grid=(16,16): bx = 64-col tile, by = 128-row tile. block=256.
#define COLS_B 64
#define ROWS_B 128
__global__ __launch_bounds__(256) void k5_out(const float* __restrict__ xf,
                                              float* __restrict__ out) {
    int tid  = threadIdx.x;
    int cidx = tid & 15;          // which float4 within the 64-col tile
    int ridx = tid >> 4;          // 0..15
    int col  = blockIdx.x * COLS_B + cidx * 4;

    float4 m = *(const float4*)(g_mean + col);
    float4 a = *(const float4*)(g_a + col);
    float4 b = *(const float4*)(g_b + col);

#pragma unroll
    for (int j = 0; j < ROWS_B / 16; j++) {     // 8 rows per thread
        int row = blockIdx.y * ROWS_B + ridx + j * 16;
        float4 x = *(const float4*)(xf + (size_t)row * XF + col);
        float4 v;
        v.x = fmaxf(x.x - m.x, 0.f) * a.x + b.x;
        v.y = fmaxf(x.y - m.y, 0.f) * a.y + b.y;
        v.z = fmaxf(x.z - m.z, 0.f) * a.z + b.z;
        v.w = fmaxf(x.w - m.w, 0.f) * a.w + b.w;

        float* orow = out + (size_t)row * (G * XF) + col;
#pragma unroll
        for (int k = 0; k < G; k++)
            __stcs((float4*)(orow + (size_t)k * XF), v);
    }
}

extern "C" void kernel_launch(void* const* d_in, const int* in_sizes, int n_in,
                              void* d_out, int out_size) {
    const float* xf = (const float*)d_in[0];
    const float* wp = (const float*)d_in[1];
    float* out = (float*)d_out;

    k1_sum<<<CH, 256>>>(xf);
    kf1_mean<<<XF / 32, 256>>>();
    k3_stats<<<CH, 256>>>(xf);
    kf2_ab<<<XF / 32, 256>>>(wp);
    k5_out<<<dim3(XF / COLS_B, BATCH / ROWS_B), 256>>>(xf, out);
}

// round 7
// speedup vs baseline: 1.4922x; 1.2315x over previous
#include <cuda_runtime.h>
#include <math.h>

#define BATCH 2048
#define XF    1024
#define XF4   (XF / 4)
#define G     16

#define CH    32                // row chunks (64 rows each)
#define RPCH  (BATCH / CH)      // 64 rows per chunk
#define RPT   8                 // rows per thread inside a chunk

// Scratch (allocation-free: __device__ globals)
__device__ float g_p0[CH * XF];     // per-chunk column sums of xf
__device__ float g_p1[CH * XF];     // per-chunk sums of relu(x-mean)
__device__ float g_p2[CH * XF];     // per-chunk sums of squares
__device__ float g_mean[XF];

// ---------------------------------------------------------------------------
// K1: partial column sums. grid=(8,32): bx = 128-col group, by = 64-row chunk.
// block=256: c4 = tid&31 (float4 col in group), rg = tid>>5 (8-row subgroup).
// In-block smem reduction folds the 8 subgroups -> one partial per chunk.
__global__ __launch_bounds__(256) void k1_sum(const float* __restrict__ xf) {
    __shared__ float4 sh[8][32];
    int c4 = threadIdx.x & 31, rg = threadIdx.x >> 5;
    int col4 = blockIdx.x * 32 + c4;
    int row0 = blockIdx.y * RPCH + rg * RPT;

    const float4* p = (const float4*)xf + (size_t)row0 * XF4 + col4;
    float4 s = make_float4(0.f, 0.f, 0.f, 0.f);
#pragma unroll
    for (int r = 0; r < RPT; r++) {
        float4 x = p[(size_t)r * XF4];
        s.x += x.x; s.y += x.y; s.z += x.z; s.w += x.w;
    }
    sh[rg][c4] = s;
    __syncthreads();
    if (rg == 0) {
        float4 t = sh[0][c4];
#pragma unroll
        for (int i = 1; i < 8; i++) {
            float4 u = sh[i][c4];
            t.x += u.x; t.y += u.y; t.z += u.z; t.w += u.w;
        }
        ((float4*)(g_p0 + blockIdx.y * XF))[col4] = t;
    }
}

// ---------------------------------------------------------------------------
// K2: prologue folds the 32 mean-partials (split across the 8 subgroups,
// smem tree), then computes partial sum/sumsq of relu(x - mean).
__global__ __launch_bounds__(256) void k2_stats(const float* __restrict__ xf) {
    __shared__ float4 sh[8][32];
    __shared__ float4 shm[32];
    int c4 = threadIdx.x & 31, rg = threadIdx.x >> 5;
    int col4 = blockIdx.x * 32 + c4;
    int row0 = blockIdx.y * RPCH + rg * RPT;

    // mean fold: subgroup rg folds chunks [rg*4, rg*4+4)
    {
        float4 s = make_float4(0.f, 0.f, 0.f, 0.f);
#pragma unroll
        for (int i = 0; i < 4; i++) {
            float4 u = ((const float4*)(g_p0 + (rg * 4 + i) * XF))[col4];
            s.x += u.x; s.y += u.y; s.z += u.z; s.w += u.w;
        }
        sh[rg][c4] = s;
    }
    __syncthreads();
    if (rg == 0) {
        float4 t = sh[0][c4];
#pragma unroll
        for (int i = 1; i < 8; i++) {
            float4 u = sh[i][c4];
            t.x += u.x; t.y += u.y; t.z += u.z; t.w += u.w;
        }
        const float inv = 1.0f / BATCH;
        t.x *= inv; t.y *= inv; t.z *= inv; t.w *= inv;
        shm[c4] = t;
        if (blockIdx.y == 0) ((float4*)g_mean)[col4] = t;
    }
    __syncthreads();
    float4 m = shm[c4];

    // stats pass: 8 rows per thread
    const float4* p = (const float4*)xf + (size_t)row0 * XF4 + col4;
    float4 s1 = make_float4(0.f, 0.f, 0.f, 0.f);
    float4 s2 = make_float4(0.f, 0.f, 0.f, 0.f);
#pragma unroll
    for (int r = 0; r < RPT; r++) {
        float4 x = p[(size_t)r * XF4];
        float vx = fmaxf(x.x - m.x, 0.f);
        float vy = fmaxf(x.y - m.y, 0.f);
        float vz = fmaxf(x.z - m.z, 0.f);
        float vw = fmaxf(x.w - m.w, 0.f);
        s1.x += vx; s1.y += vy; s1.z += vz; s1.w += vw;
        s2.x += vx * vx; s2.y += vy * vy; s2.z += vz * vz; s2.w += vw * vw;
    }
    __syncthreads();                       // reuse sh
    sh[rg][c4] = s1;
    __syncthreads();
    if (rg == 0) {
        float4 t = sh[0][c4];
#pragma unroll
        for (int i = 1; i < 8; i++) {
            float4 u = sh[i][c4];
            t.x += u.x; t.y += u.y; t.z += u.z; t.w += u.w;
        }
        ((float4*)(g_p1 + blockIdx.y * XF))[col4] = t;
    }
    __syncthreads();
    sh[rg][c4] = s2;
    __syncthreads();
    if (rg == 0) {
        float4 t = sh[0][c4];
#pragma unroll
        for (int i = 1; i < 8; i++) {
            float4 u = sh[i][c4];
            t.x += u.x; t.y += u.y; t.z += u.z; t.w += u.w;
        }
        ((float4*)(g_p2 + blockIdx.y * XF))[col4] = t;
    }
}

// ---------------------------------------------------------------------------
// K3: prologue folds the 32 stats-partials for this block's 64 columns into
// per-column affine (a,b); then writes the 16-way tiled output with
// streaming stores. grid=(16,16): bx = 64-col tile, by = 128-row tile.
#define COLS_B 64
#define ROWS_B 128
__global__ __launch_bounds__(256) void k3_out(const float* __restrict__ xf,
                                              const float* __restrict__ wp,
                                              float* __restrict__ out) {
    __shared__ float sh1[4][COLS_B], sh2[4][COLS_B];
    __shared__ float s_m[COLS_B], s_a[COLS_B], s_b[COLS_B];
    int tid = threadIdx.x;
    int col0 = blockIdx.x * COLS_B;

    {   // fold: cc = col, gg = 8-chunk group
        int cc = tid & 63, gg = tid >> 6;
        int col = col0 + cc;
        float s1 = 0.f, s2 = 0.f;
#pragma unroll
        for (int i = 0; i < 8; i++) {
            int idx = (gg * 8 + i) * XF + col;
            s1 += g_p1[idx];
            s2 += g_p2[idx];
        }
        sh1[gg][cc] = s1;
        sh2[gg][cc] = s2;
    }
    __syncthreads();
    if (tid < COLS_B) {
        float s1 = sh1[0][tid] + sh1[1][tid] + sh1[2][tid] + sh1[3][tid];
        float s2 = sh2[0][tid] + sh2[1][tid] + sh2[2][tid] + sh2[3][tid];
        float mu  = s1 * (1.0f / BATCH);
        float var = (s2 - (float)BATCH * mu * mu) * (1.0f / (BATCH - 1));
        float a   = wp[0] * rsqrtf(var);
        s_m[tid] = g_mean[col0 + tid];
        s_a[tid] = a;
        s_b[tid] = -a * mu;
    }
    __syncthreads();

    int cidx = tid & 15;          // which float4 within the 64-col tile
    int ridx = tid >> 4;          // 0..15
    int col  = col0 + cidx * 4;

    float4 m = *(const float4*)(s_m + cidx * 4);
    float4 a = *(const float4*)(s_a + cidx * 4);
    float4 b = *(const float4*)(s_b + cidx * 4);

#pragma unroll
    for (int j = 0; j < ROWS_B / 16; j++) {     // 8 rows per thread
        int row = blockIdx.y * ROWS_B + ridx + j * 16;
        float4 x = *(const float4*)(xf + (size_t)row * XF + col);
        float4 v;
        v.x = fmaxf(x.x - m.x, 0.f) * a.x + b.x;
        v.y = fmaxf(x.y - m.y, 0.f) * a.y + b.y;
        v.z = fmaxf(x.z - m.z, 0.f) * a.z + b.z;
        v.w = fmaxf(x.w - m.w, 0.f) * a.w + b.w;

        float* orow = out + (size_t)row * (G * XF) + col;
#pragma unroll
        for (int k = 0; k < G; k++)
            __stcs((float4*)(orow + (size_t)k * XF), v);
    }
}

extern "C" void kernel_launch(void* const* d_in, const int* in_sizes, int n_in,
                              void* d_out, int out_size) {
    const float* xf = (const float*)d_in[0];
    const float* wp = (const float*)d_in[1];
    float* out = (float*)d_out;

    k1_sum<<<dim3(8, CH), 256>>>(xf);
    k2_stats<<<dim3(8, CH), 256>>>(xf);
    k3_out<<<dim3(XF / COLS_B, BATCH / ROWS_B), 256>>>(xf, wp, out);
}